// round 6
// baseline (speedup 1.0000x reference)
#include <cuda_runtime.h>
#include <math.h>

#define BATCH 16384
#define NUM_CLASSES 1604
#define C4 (NUM_CLASSES / 4)      // 401 float4 per row
#define WARPS_PER_BLOCK 8
#define THREADS (WARPS_PER_BLOCK * 32)
#define EPS 1e-6f

__global__ void zero_out_kernel(float* out) {
    if (threadIdx.x == 0) out[0] = 0.0f;
}

// One warp per sample. No max-subtraction (sigma is shift-invariant; EPS
// perturbation ~1e-7 relative, gate is 1e-3; measured margin 5e-7).
// __launch_bounds__(256,4): give ptxas ~64 regs so it can front-batch
// LDG.128s (MLP ~8-16) instead of the 32-reg MLP~4 version.
__global__ __launch_bounds__(THREADS, 4)
void seesaw_loss_kernel(const float* __restrict__ logits,
                        const float* __restrict__ s,
                        const int* __restrict__ targets,
                        float* __restrict__ out) {
    const int warp = threadIdx.x >> 5;
    const int lane = threadIdx.x & 31;
    const int b = blockIdx.x * WARPS_PER_BLOCK + warp;
    const int t = targets[b];

    const float4* __restrict__ lrow =
        reinterpret_cast<const float4*>(logits + (size_t)b * NUM_CLASSES);
    const float4* __restrict__ srow =
        reinterpret_cast<const float4*>(s + (size_t)t * NUM_CLASSES);

    // denom = sum_j s[t,j] * exp(x_j); the j==t term equals num_t (s[t,t]==1).
    // 4 independent accumulators: FFMA dep chain broken to every 4th step,
    // loads for 4 iterations issue back-to-back.
    float a0 = 0.0f, a1 = 0.0f, a2 = 0.0f, a3 = 0.0f;

    int i = lane;
    // C4 = 401 = 3 * (4*32) + 17, so 3 full unroll-4 rounds per lane (+ tail).
    #pragma unroll 1
    for (; i + 96 < C4; i += 128) {
        float4 x0 = lrow[i];
        float4 x1 = lrow[i + 32];
        float4 x2 = lrow[i + 64];
        float4 x3 = lrow[i + 96];
        float4 w0 = srow[i];
        float4 w1 = srow[i + 32];
        float4 w2 = srow[i + 64];
        float4 w3 = srow[i + 96];
        a0 += w0.x * __expf(x0.x) + w0.y * __expf(x0.y)
            + w0.z * __expf(x0.z) + w0.w * __expf(x0.w);
        a1 += w1.x * __expf(x1.x) + w1.y * __expf(x1.y)
            + w1.z * __expf(x1.z) + w1.w * __expf(x1.w);
        a2 += w2.x * __expf(x2.x) + w2.y * __expf(x2.y)
            + w2.z * __expf(x2.z) + w2.w * __expf(x2.w);
        a3 += w3.x * __expf(x3.x) + w3.y * __expf(x3.y)
            + w3.z * __expf(x3.z) + w3.w * __expf(x3.w);
    }
    // Tail: remaining i < C4 (at most one strided element per lane here).
    for (; i < C4; i += 32) {
        float4 x = lrow[i];
        float4 w = srow[i];
        a0 += w.x * __expf(x.x) + w.y * __expf(x.y)
            + w.z * __expf(x.z) + w.w * __expf(x.w);
    }

    float sum = (a0 + a1) + (a2 + a3);

    // Warp sum.
    #pragma unroll
    for (int o = 16; o > 0; o >>= 1)
        sum += __shfl_xor_sync(0xFFFFFFFFu, sum, o);

    __shared__ float sh_loss[WARPS_PER_BLOCK];
    if (lane == 0) {
        float xt = logits[(size_t)b * NUM_CLASSES + t];
        float num_t = __expf(xt);
        float sigma = num_t / (sum + EPS);
        sh_loss[warp] = -__logf(sigma + EPS);
    }
    __syncthreads();

    if (threadIdx.x == 0) {
        float acc = 0.0f;
        #pragma unroll
        for (int w = 0; w < WARPS_PER_BLOCK; w++) acc += sh_loss[w];
        atomicAdd(out, acc * (1.0f / (float)BATCH));
    }
}

extern "C" void kernel_launch(void* const* d_in, const int* in_sizes, int n_in,
                              void* d_out, int out_size) {
    const float* logits  = (const float*)d_in[0];
    const float* s       = (const float*)d_in[1];
    const int*   targets = (const int*)d_in[2];
    float* out = (float*)d_out;

    zero_out_kernel<<<1, 32>>>(out);
    seesaw_loss_kernel<<<BATCH / WARPS_PER_BLOCK, THREADS>>>(logits, s, targets, out);
}